// round 1
// baseline (speedup 1.0000x reference)
#include <cuda_runtime.h>
#include <math.h>

#define BB 32
#define TT 50
#define SS 2048
#define CC 8
#define FF 32
#define SH 1024
#define NG 128          // 4*F gates
#define RDIM 80         // 16 (x patch) + 64 (h patch)
#define POSB 64         // positions per block
#define NWARP 8
#define NP 8            // positions per warp
#define NTHREADS 256

// Persistent device state (re-initialized every kernel_launch call)
__device__ float g_h[2][BB][SH + 1][FF];   // double-buffered h, +1 halo row (stays 0)
__device__ float g_c[BB][SH][FF];
__device__ float4 g_w4[RDIM][FF];          // [r][f] -> (gate0, gate1, gate2, gate3)

__device__ __forceinline__ float hsig(float x) {
    return __saturatef(fmaf(x, 0.2f, 0.5f));
}

__global__ void zero_state_kernel() {
    size_t idx = (size_t)blockIdx.x * blockDim.x + threadIdx.x;
    size_t stride = (size_t)gridDim.x * blockDim.x;
    float* h = &g_h[0][0][0][0];
    float* c = &g_c[0][0][0];
    const size_t nh = (size_t)2 * BB * (SH + 1) * FF;
    const size_t nc = (size_t)BB * SH * FF;
    for (size_t i = idx; i < nh; i += stride) h[i] = 0.0f;
    for (size_t i = idx; i < nc; i += stride) c[i] = 0.0f;
}

// Repack weights: row r of the 80-wide reduction.
// r in [0,16):  x patch, k = r>>3, c = r&7     -> kernel[k][c][g]
// r in [16,80): h patch, rr=r-16, k=rr>>5, ff=rr&31 -> rec_kernel[k][ff][g]
__global__ void prep_w_kernel(const float* __restrict__ kern,
                              const float* __restrict__ rk) {
    int i = blockIdx.x * blockDim.x + threadIdx.x;
    if (i >= RDIM * FF) return;
    int r = i / FF, f = i % FF;
    const float* src;
    if (r < 16) {
        int k = r >> 3, c = r & 7;
        src = kern + (k * CC + c) * NG;
    } else {
        int rr = r - 16;
        int k = rr >> 5, ff = rr & 31;
        src = rk + (k * FF + ff) * NG;
    }
    g_w4[r][f] = make_float4(src[f], src[32 + f], src[64 + f], src[96 + f]);
}

// One LSTM timestep. Grid: (SH/POSB, BB). 256 threads.
// Dynamic smem: w4s[80][32] float4 (40960B) | xs[64*16] (4096B) | hs[65][32] (8320B)
__global__ __launch_bounds__(NTHREADS)
void step_kernel(const float* __restrict__ x, const float* __restrict__ bias, int t) {
    extern __shared__ float smem[];
    float4* w4s = (float4*)smem;                 // 2560 float4
    float* xs = smem + RDIM * FF * 4;            // 1024 floats
    float* hs = xs + POSB * 16;                  // 65*32 floats

    const int b = blockIdx.y;
    const int p0 = blockIdx.x * POSB;
    const int tid = threadIdx.x;
    const int par = t & 1;

    // cooperative loads
    {
        const float4* wsrc = &g_w4[0][0];
        #pragma unroll
        for (int i = tid; i < RDIM * FF; i += NTHREADS) w4s[i] = wsrc[i];
        // x tile: 128 spatial * 8 channels contiguous = 1024 floats
        const float* xsrc = x + (((size_t)b * TT + t) * SS + 2 * p0) * CC;
        #pragma unroll
        for (int i = tid; i < POSB * 16; i += NTHREADS) xs[i] = xsrc[i];
        // h tile with halo: (POSB+1)*32 floats
        const float* hsrc = &g_h[par][b][p0][0];
        #pragma unroll
        for (int i = tid; i < (POSB + 1) * FF; i += NTHREADS) hs[i] = hsrc[i];
    }
    __syncthreads();

    const int f = tid & 31;
    const int w = tid >> 5;
    const int pl = w * NP;   // warp's local position base

    float acc[NP][4];
    {
        const float b0 = bias[f], b1 = bias[32 + f], b2 = bias[64 + f], b3 = bias[96 + f];
        #pragma unroll
        for (int j = 0; j < NP; j++) {
            acc[j][0] = b0; acc[j][1] = b1; acc[j][2] = b2; acc[j][3] = b3;
        }
    }

    // x-patch contribution (r = 0..15)
    #pragma unroll
    for (int r = 0; r < 16; r++) {
        float4 wv = w4s[r * FF + f];
        #pragma unroll
        for (int j = 0; j < NP; j++) {
            float pv = xs[(pl + j) * 16 + r];
            acc[j][0] = fmaf(pv, wv.x, acc[j][0]);
            acc[j][1] = fmaf(pv, wv.y, acc[j][1]);
            acc[j][2] = fmaf(pv, wv.z, acc[j][2]);
            acc[j][3] = fmaf(pv, wv.w, acc[j][3]);
        }
    }
    // h-patch contribution (r = 16..79): k in {0,1}, ff in [0,32)
    #pragma unroll
    for (int k = 0; k < 2; k++) {
        #pragma unroll 8
        for (int ff = 0; ff < FF; ff++) {
            float4 wv = w4s[(16 + k * FF + ff) * FF + f];
            #pragma unroll
            for (int j = 0; j < NP; j++) {
                float pv = hs[(pl + j + k) * FF + ff];
                acc[j][0] = fmaf(pv, wv.x, acc[j][0]);
                acc[j][1] = fmaf(pv, wv.y, acc[j][1]);
                acc[j][2] = fmaf(pv, wv.z, acc[j][2]);
                acc[j][3] = fmaf(pv, wv.w, acc[j][3]);
            }
        }
    }

    // LSTM cell update
    #pragma unroll
    for (int j = 0; j < NP; j++) {
        const int p = p0 + pl + j;
        float cold = g_c[b][p][f];
        float i_g = hsig(acc[j][0]);
        float f_g = hsig(acc[j][1]);
        float cn = f_g * cold + i_g * tanhf(acc[j][2]);
        float o_g = hsig(acc[j][3]);
        float hn = o_g * tanhf(cn);
        g_c[b][p][f] = cn;
        g_h[1 - par][b][p][f] = hn;
    }
}

// out[b] = sum(h_final[b] * dense_w) + dense_b  (h_final lives in parity-0 buffer)
__global__ __launch_bounds__(256)
void dense_kernel(const float* __restrict__ dw, const float* __restrict__ db,
                  float* __restrict__ out) {
    const int b = blockIdx.x;
    const float* h = &g_h[0][b][0][0];   // rows 0..SH-1 contiguous, halo at end
    float s = 0.0f;
    for (int i = threadIdx.x; i < SH * FF; i += 256) s += h[i] * dw[i];
    // block reduce
    #pragma unroll
    for (int off = 16; off > 0; off >>= 1) s += __shfl_down_sync(0xffffffffu, s, off);
    __shared__ float red[8];
    int lane = threadIdx.x & 31, wid = threadIdx.x >> 5;
    if (lane == 0) red[wid] = s;
    __syncthreads();
    if (wid == 0) {
        s = (lane < 8) ? red[lane] : 0.0f;
        #pragma unroll
        for (int off = 4; off > 0; off >>= 1) s += __shfl_down_sync(0xffffffffu, s, off);
        if (lane == 0) out[b] = s + db[0];
    }
}

extern "C" void kernel_launch(void* const* d_in, const int* in_sizes, int n_in,
                              void* d_out, int out_size) {
    const float* x    = (const float*)d_in[0];  // (32,50,2048,8)
    const float* kern = (const float*)d_in[1];  // (2,8,128)
    const float* rk   = (const float*)d_in[2];  // (2,32,128)
    const float* bias = (const float*)d_in[3];  // (128,)
    const float* dw   = (const float*)d_in[4];  // (32768,1)
    const float* db   = (const float*)d_in[5];  // (1,)
    float* out = (float*)d_out;                  // (32,1)

    const int smem_bytes = RDIM * FF * 16 + POSB * 16 * 4 + (POSB + 1) * FF * 4; // 53376
    static int configured = 0;
    if (!configured) {
        cudaFuncSetAttribute(step_kernel, cudaFuncAttributeMaxDynamicSharedMemorySize,
                             smem_bytes);
        configured = 1;
    }

    zero_state_kernel<<<512, 256>>>();
    prep_w_kernel<<<(RDIM * FF + 255) / 256, 256>>>(kern, rk);

    dim3 grid(SH / POSB, BB);
    for (int t = 0; t < TT; t++) {
        step_kernel<<<grid, NTHREADS, smem_bytes>>>(x, bias, t);
    }
    dense_kernel<<<BB, 256>>>(dw, db, out);
}